// round 15
// baseline (speedup 1.0000x reference)
#include <cuda_runtime.h>

#define DI static __device__ __forceinline__
typedef unsigned long long ull;

namespace {
constexpr int B = 2, S = 512, H = 128, A = 7;
constexpr int BS = B * S;
constexpr float LOG2E = 1.4426950408889634f;
constexpr float LN2   = 0.6931471805599453f;
constexpr float TK0   = 0.7978845608028654f;          // sqrt(2/pi)
constexpr float TK1   = TK0 * 0.044715f;
constexpr float GK0   = -2.0f * LOG2E * TK0;          // sigmoid-form consts (action head)
constexpr float GK1   = GK0 * 0.044715f;
constexpr float EPS   = 1e-5f;
}

// scratch: 2 = hd_left, 4 = hd_right
__device__ __align__(16) float g_pre[5][BS * H];
// hv transposed: g_hvT[head][q2][b*S + j] = float4(ch 4q2..4q2+3 of row j)
__device__ __align__(16) float4 g_hvT[2][H / 4][BS];
__device__ float g_logits[BS * A];

DI float ex2a(float x){ float y; asm("ex2.approx.ftz.f32 %0, %1;" : "=f"(y) : "f"(x)); return y; }
DI float rcpa(float x){ float y; asm("rcp.approx.ftz.f32 %0, %1;" : "=f"(y) : "f"(x)); return y; }
DI float lg2a(float x){ float y; asm("lg2.approx.ftz.f32 %0, %1;" : "=f"(y) : "f"(x)); return y; }
DI float rsqa(float x){ float y; asm("rsqrt.approx.ftz.f32 %0, %1;" : "=f"(y) : "f"(x)); return y; }
DI float tanha(float x){ float y; asm("tanh.approx.f32 %0, %1;" : "=f"(y) : "f"(x)); return y; }

// ---- packed f32x2 helpers (sm_103a) ----
DI ull pk2(float x, float y){ ull r; asm("mov.b64 %0, {%1, %2};" : "=l"(r) : "f"(x), "f"(y)); return r; }
DI void upk2(ull v, float& x, float& y){ asm("mov.b64 {%0, %1}, %2;" : "=f"(x), "=f"(y) : "l"(v)); }
DI ull add2(ull a, ull b){ ull r; asm("add.rn.f32x2 %0, %1, %2;" : "=l"(r) : "l"(a), "l"(b)); return r; }
DI ull mul2(ull a, ull b){ ull r; asm("mul.rn.f32x2 %0, %1, %2;" : "=l"(r) : "l"(a), "l"(b)); return r; }
DI ull fma2(ull a, ull b, ull c){ ull r; asm("fma.rn.f32x2 %0, %1, %2, %3;" : "=l"(r) : "l"(a), "l"(b), "l"(c)); return r; }

// exact-ish gelu (sigmoid form, f32) for the action head
DI float gelu_f(float x){
  float x2 = x * x;
  float w  = x * fmaf(GK1, x2, GK0);
  return x * rcpa(1.0f + ex2a(w));
}

DI float wredmax(float v){
  #pragma unroll
  for (int o = 16; o; o >>= 1) v = fmaxf(v, __shfl_xor_sync(0xffffffffu, v, o));
  return v;
}
DI float wredsum(float v){
  #pragma unroll
  for (int o = 16; o; o >>= 1) v += __shfl_xor_sync(0xffffffffu, v, o);
  return v;
}

// ---------------- P1: five GEMMs, smem-staged W (double-buffered) -----------
// grid (BS/16, 5) = 320 CTAs, block 256 = 8 warps, 2 rows/warp.
// W read from gmem ONCE per CTA via ping-pong smem chunks (no L1 thrash).
// m=0: fused action epilogue -> g_logits. m=1,3: transposed store to g_hvT.
__global__ void __launch_bounds__(256) k_gemm(
    const float* __restrict__ x,
    const float* __restrict__ W0, const float* __restrict__ Bi0,
    const float* __restrict__ W1, const float* __restrict__ Bi1,
    const float* __restrict__ W2, const float* __restrict__ Bi2,
    const float* __restrict__ W3, const float* __restrict__ Bi3,
    const float* __restrict__ W4, const float* __restrict__ Bi4,
    const float* __restrict__ lng, const float* __restrict__ lnb,
    const float* __restrict__ aw2, const float* __restrict__ ab2)
{
  __shared__ __align__(16) float xs[16][H];
  __shared__ __align__(16) float wbuf[2][16 * H];   // 2 x 8KB W chunks
  int m = blockIdx.y;
  const float* W = W0; const float* bias = Bi0;
  if      (m == 1){ W = W1; bias = Bi1; }
  else if (m == 2){ W = W2; bias = Bi2; }
  else if (m == 3){ W = W3; bias = Bi3; }
  else if (m == 4){ W = W4; bias = Bi4; }

  int r0 = blockIdx.x * 16;
  int t  = threadIdx.x;
  int wid = t >> 5, lane = t & 31;
  int c0 = lane * 4;
  int rt = wid * 2;

  // load 16 rows of x (512 float4, 2 per thread)
  #pragma unroll
  for (int k = 0; k < 2; ++k) {
    int idx = t + k * 256;
    *(float4*)&xs[idx >> 5][(idx & 31) * 4] =
        *(const float4*)&x[(r0 + (idx >> 5)) * H + (idx & 31) * 4];
  }

  // prefetch W chunk 0 (rows 0..15 = first 512 float4)
  const float4* Wv = (const float4*)W;
  float4 pf0 = Wv[t], pf1 = Wv[t + 256];

  float4 bv = *(const float4*)&bias[c0];
  float acc[2][4];
  #pragma unroll
  for (int i = 0; i < 2; ++i){ acc[i][0]=bv.x; acc[i][1]=bv.y; acc[i][2]=bv.z; acc[i][3]=bv.w; }

  for (int c = 0; c < 8; ++c) {
    float4* wb = (float4*)wbuf[c & 1];
    __syncthreads();                    // buffer (c&1) free (compute from c-2 done)
    wb[t] = pf0; wb[t + 256] = pf1;
    __syncthreads();
    if (c < 7) {
      const float4* Wn = Wv + (c + 1) * 512;
      pf0 = Wn[t]; pf1 = Wn[t + 256];
    }
    const float* wbf = wbuf[c & 1];
    #pragma unroll
    for (int hh = 0; hh < 16; ++hh) {
      int h = c * 16 + hh;
      float4 w4 = *(const float4*)&wbf[hh * H + c0];
      float xv0 = xs[rt][h], xv1 = xs[rt + 1][h];
      acc[0][0] = fmaf(xv0, w4.x, acc[0][0]);
      acc[0][1] = fmaf(xv0, w4.y, acc[0][1]);
      acc[0][2] = fmaf(xv0, w4.z, acc[0][2]);
      acc[0][3] = fmaf(xv0, w4.w, acc[0][3]);
      acc[1][0] = fmaf(xv1, w4.x, acc[1][0]);
      acc[1][1] = fmaf(xv1, w4.y, acc[1][1]);
      acc[1][2] = fmaf(xv1, w4.z, acc[1][2]);
      acc[1][3] = fmaf(xv1, w4.w, acc[1][3]);
    }
  }

  if (m == 0) {
    // fused action head: each warp owns rows rt, rt+1 completely
    float4 lg4 = *(const float4*)&lng[c0];
    float4 lb4 = *(const float4*)&lnb[c0];
    #pragma unroll
    for (int i = 0; i < 2; ++i) {
      float y0 = gelu_f(acc[i][0]), y1 = gelu_f(acc[i][1]);
      float y2 = gelu_f(acc[i][2]), y3 = gelu_f(acc[i][3]);
      float s1 = wredsum(y0 + y1 + y2 + y3);
      float s2 = wredsum(y0*y0 + y1*y1 + y2*y2 + y3*y3);
      float mean = s1 * (1.0f / H);
      float var  = fmaf(-mean, mean, s2 * (1.0f / H));
      float rstd = rsqa(var + EPS);
      float z0 = fmaf((y0 - mean) * rstd, lg4.x, lb4.x);
      float z1 = fmaf((y1 - mean) * rstd, lg4.y, lb4.y);
      float z2 = fmaf((y2 - mean) * rstd, lg4.z, lb4.z);
      float z3 = fmaf((y3 - mean) * rstd, lg4.w, lb4.w);
      float r[7];
      #pragma unroll
      for (int a = 0; a < A; ++a) {
        float p = fmaf(z0, aw2[(c0+0)*A+a],
                  fmaf(z1, aw2[(c0+1)*A+a],
                  fmaf(z2, aw2[(c0+2)*A+a], z3 * aw2[(c0+3)*A+a])));
        r[a] = wredsum(p);
      }
      if (lane == 0) {
        int row = r0 + rt + i;
        #pragma unroll
        for (int a = 0; a < A; ++a) g_logits[row * A + a] = r[a] + ab2[a];
      }
    }
  } else if (m == 1 || m == 3) {
    int hh = (m == 1) ? 0 : 1;
    float4* st = (float4*)wbuf;          // reuse W buffers (16x33 float4 fits 16KB)
    __syncthreads();
    #pragma unroll
    for (int i = 0; i < 2; ++i){
      float4 o; o.x=acc[i][0]; o.y=acc[i][1]; o.z=acc[i][2]; o.w=acc[i][3];
      st[(rt + i) * 33 + lane] = o;
    }
    __syncthreads();
    #pragma unroll
    for (int k = 0; k < 2; ++k) {
      int idx = t + k * 256;
      int q2 = idx >> 4, rr = idx & 15;
      g_hvT[hh][q2][r0 + rr] = st[rr * 33 + q2];
    }
  } else {
    #pragma unroll
    for (int i = 0; i < 2; ++i){
      float4 o; o.x=acc[i][0]; o.y=acc[i][1]; o.z=acc[i][2]; o.w=acc[i][3];
      *(float4*)&g_pre[m][(r0 + rt + i) * H + c0] = o;
    }
  }
}

// ---------------- P2: action log_softmax over dim 1 (sequence) ----------------
__global__ void __launch_bounds__(512) k_actsm(float* __restrict__ out)
{
  int b = blockIdx.x / A, a = blockIdx.x % A;
  int s = threadIdx.x;
  float v = g_logits[(b * S + s) * A + a];

  __shared__ float red[16];
  __shared__ float bmax_s, bsum_s;
  int wid = s >> 5, lane = s & 31;

  float m = wredmax(v);
  if (lane == 0) red[wid] = m;
  __syncthreads();
  if (s < 32){
    float tt = (s < 16) ? red[s] : -3.4e38f;
    tt = wredmax(tt);
    if (s == 0) bmax_s = tt;
  }
  __syncthreads();
  float bmax = bmax_s;
  float e = ex2a((v - bmax) * LOG2E);
  float sm = wredsum(e);
  __syncthreads();
  if (lane == 0) red[wid] = sm;
  __syncthreads();
  if (s < 32){
    float tt = (s < 16) ? red[s] : 0.0f;
    tt = wredsum(tt);
    if (s == 0) bsum_s = tt;
  }
  __syncthreads();
  out[(b * S + s) * A + a] = v - bmax - lg2a(bsum_s) * LN2;
}

// ---------------- P4: pointer heads (f32x2 + f32 tanh, 4 i-rows/warp) --------
// grid (S/4, B, 2) = 512 CTAs, block 256 = 8 j-groups of 64 j each.
__global__ void __launch_bounds__(256, 4) k_ptr(
    const float* __restrict__ lg, const float* __restrict__ lb,
    const float* __restrict__ lpw, const float* __restrict__ lpb,
    const float* __restrict__ rg, const float* __restrict__ rb,
    const float* __restrict__ rpw, const float* __restrict__ rpb,
    float* __restrict__ out)
{
  int head = blockIdx.z, b = blockIdx.y;
  int i0 = blockIdx.x * 4;
  const float* gv = head ? rg  : lg;
  const float* bv = head ? rb  : lb;
  const float* pw = head ? rpw : lpw;
  const float* pb = head ? rpb : lpb;
  const float* hd = g_pre[2 + 2 * head] + b * S * H;   // indexed by i

  __shared__ __align__(16) float hds[4][H];
  __shared__ __align__(16) float wgh[H];
  __shared__ float redc[4][2];
  __shared__ float cc2[2];
  __shared__ float gmaxs[8][4], gsums[8][4];

  int tid  = threadIdx.x;
  int wid  = tid >> 5, lane = tid & 31;
  int g    = wid;             // j-group (0..7), 64 j each

  if (tid < 128) {
    float p  = pw[tid];
    float wg = gv[tid] * p;
    float tb = bv[tid] * p;
    wgh[tid] = wg;
    float r1 = wredsum(wg), r2 = wredsum(tb);
    if (lane == 0){ redc[wid][0] = r1; redc[wid][1] = r2; }
  }
  for (int idx = tid; idx < 4 * H; idx += 256)
    hds[idx >> 7][idx & (H - 1)] = hd[(i0 + (idx >> 7)) * H + (idx & (H - 1))];
  __syncthreads();
  if (tid == 0){
    cc2[0] = redc[0][0] + redc[1][0] + redc[2][0] + redc[3][0];
    cc2[1] = redc[0][1] + redc[1][1] + redc[2][1] + redc[3][1] + pb[0];
  }
  __syncthreads();
  float c1 = cc2[0], c2 = cc2[1];

  const ull K0p = pk2(TK0, TK0);
  const ull K1p = pk2(TK1, TK1);
  const ull* wr = (const ull*)&wgh[0];

  float sc[4][2];   // [i-row][tile]

  #pragma unroll
  for (int tile = 0; tile < 2; ++tile) {
    int jb = g * 64 + tile * 32;
    const ulonglong2* ap = (const ulonglong2*)&g_hvT[head][0][b * S + jb + lane];

    ull s1[4], s2[4], s3[4];
    #pragma unroll
    for (int r = 0; r < 4; ++r){ s1[r] = 0; s2[r] = 0; s3[r] = 0; }

    #pragma unroll 8
    for (int q2 = 0; q2 < 32; ++q2) {
      ulonglong2 a2 = ap[q2 * BS];
      #pragma unroll
      for (int half = 0; half < 2; ++half) {
        ull a = half ? a2.y : a2.x;
        ull w = wr[q2 * 2 + half];
        #pragma unroll
        for (int r = 0; r < 4; ++r) {
          ull d  = ((const ull*)&hds[r][0])[q2 * 2 + half];
          ull x  = add2(a, d);
          ull x2 = mul2(x, x);
          ull p  = fma2(K1p, x2, K0p);
          ull u  = mul2(x, p);
          float u0f, u1f; upk2(u, u0f, u1f);
          ull t  = pk2(tanha(u0f), tanha(u1f));
          ull z  = fma2(x, t, x);          // z = 2*gelu(x)
          s1[r] = add2(s1[r], z);
          s2[r] = fma2(z, z, s2[r]);
          s3[r] = fma2(z, w, s3[r]);
        }
      }
    }
    #pragma unroll
    for (int r = 0; r < 4; ++r) {
      float a0,a1,q0,q1,d0,d1;
      upk2(s1[r], a0, a1); upk2(s2[r], q0, q1); upk2(s3[r], d0, d1);
      float t1 = a0 + a1, t2 = q0 + q1, t3 = d0 + d1;
      float mean = t1 * (0.5f / H);                       // sum(y)/H, y = z/2
      float var  = fmaf(-mean, mean, t2 * (0.25f / H));
      float rstd = rsqa(var + EPS);
      sc[r][tile] = fmaf(rstd, fmaf(-mean, c1, 0.5f * t3), c2);
    }
  }

  // log_softmax over j: combine 8 j-groups per i-row
  float lm[4];
  #pragma unroll
  for (int r = 0; r < 4; ++r) {
    lm[r] = wredmax(fmaxf(sc[r][0], sc[r][1]));
    if (lane == 0) gmaxs[g][r] = lm[r];
  }
  __syncthreads();
  float mrow[4], ls[4];
  #pragma unroll
  for (int r = 0; r < 4; ++r) {
    float m = gmaxs[0][r];
    #pragma unroll
    for (int gg = 1; gg < 8; ++gg) m = fmaxf(m, gmaxs[gg][r]);
    mrow[r] = m;
    float s = ex2a((sc[r][0] - m) * LOG2E) + ex2a((sc[r][1] - m) * LOG2E);
    ls[r] = wredsum(s);
    if (lane == 0) gsums[g][r] = ls[r];
  }
  __syncthreads();
  float* obase = out + B * S * A + head * (B * S * S);
  #pragma unroll
  for (int r = 0; r < 4; ++r) {
    float s = gsums[0][r];
    #pragma unroll
    for (int gg = 1; gg < 8; ++gg) s += gsums[gg][r];
    float lse = lg2a(s) * LN2;
    float* orow = obase + (b * S + i0 + r) * S + g * 64;
    orow[lane]      = sc[r][0] - mrow[r] - lse;
    orow[32 + lane] = sc[r][1] - mrow[r] - lse;
  }
}

extern "C" void kernel_launch(void* const* d_in, const int* in_sizes, int n_in,
                              void* d_out, int out_size)
{
  (void)in_sizes; (void)n_in; (void)out_size;
  const float* hiddens = (const float*)d_in[0];
  const float* aw1     = (const float*)d_in[1];
  const float* ab1     = (const float*)d_in[2];
  const float* a_ln_g  = (const float*)d_in[3];
  const float* a_ln_b  = (const float*)d_in[4];
  const float* aw2     = (const float*)d_in[5];
  const float* ab2     = (const float*)d_in[6];
  const float* lhid_w  = (const float*)d_in[7];
  const float* lhid_b  = (const float*)d_in[8];
  const float* lhead_w = (const float*)d_in[9];
  const float* lhead_b = (const float*)d_in[10];
  const float* l_ln_g  = (const float*)d_in[11];
  const float* l_ln_b  = (const float*)d_in[12];
  const float* l_proj_w= (const float*)d_in[13];
  const float* l_proj_b= (const float*)d_in[14];
  const float* rhid_w  = (const float*)d_in[15];
  const float* rhid_b  = (const float*)d_in[16];
  const float* rhead_w = (const float*)d_in[17];
  const float* rhead_b = (const float*)d_in[18];
  const float* r_ln_g  = (const float*)d_in[19];
  const float* r_ln_b  = (const float*)d_in[20];
  const float* r_proj_w= (const float*)d_in[21];
  const float* r_proj_b= (const float*)d_in[22];
  float* out = (float*)d_out;

  k_gemm<<<dim3(BS / 16, 5), 256>>>(hiddens,
      aw1, ab1, lhid_w, lhid_b, lhead_w, lhead_b, rhid_w, rhid_b, rhead_w, rhead_b,
      a_ln_g, a_ln_b, aw2, ab2);
  k_actsm<<<B * A, 512>>>(out);
  k_ptr<<<dim3(S / 4, B, 2), 256>>>(l_ln_g, l_ln_b, l_proj_w, l_proj_b,
                                    r_ln_g, r_ln_b, r_proj_w, r_proj_b, out);
}

// round 16
// speedup vs baseline: 1.1368x; 1.1368x over previous
#include <cuda_runtime.h>

#define DI static __device__ __forceinline__
typedef unsigned long long ull;

namespace {
constexpr int B = 2, S = 512, H = 128, A = 7;
constexpr int BS = B * S;
constexpr float LOG2E = 1.4426950408889634f;
constexpr float LN2   = 0.6931471805599453f;
constexpr float TK0   = 0.7978845608028654f;          // sqrt(2/pi)
constexpr float TK1   = TK0 * 0.044715f;
constexpr float GK0   = -2.0f * LOG2E * TK0;          // sigmoid-form consts (action head)
constexpr float GK1   = GK0 * 0.044715f;
constexpr float EPS   = 1e-5f;
}

// scratch: 2 = hd_left, 4 = hd_right
__device__ __align__(16) float g_pre[5][BS * H];
// hv transposed: g_hvT[head][q2][b*S + j] = float4(ch 4q2..4q2+3 of row j)
__device__ __align__(16) float4 g_hvT[2][H / 4][BS];
__device__ float g_logits[BS * A];

DI float ex2a(float x){ float y; asm("ex2.approx.ftz.f32 %0, %1;" : "=f"(y) : "f"(x)); return y; }
DI float rcpa(float x){ float y; asm("rcp.approx.ftz.f32 %0, %1;" : "=f"(y) : "f"(x)); return y; }
DI float lg2a(float x){ float y; asm("lg2.approx.ftz.f32 %0, %1;" : "=f"(y) : "f"(x)); return y; }
DI float rsqa(float x){ float y; asm("rsqrt.approx.ftz.f32 %0, %1;" : "=f"(y) : "f"(x)); return y; }
DI float tanha(float x){ float y; asm("tanh.approx.f32 %0, %1;" : "=f"(y) : "f"(x)); return y; }

// ---- packed f32x2 helpers (sm_103a) ----
DI ull pk2(float x, float y){ ull r; asm("mov.b64 %0, {%1, %2};" : "=l"(r) : "f"(x), "f"(y)); return r; }
DI void upk2(ull v, float& x, float& y){ asm("mov.b64 {%0, %1}, %2;" : "=f"(x), "=f"(y) : "l"(v)); }
DI ull add2(ull a, ull b){ ull r; asm("add.rn.f32x2 %0, %1, %2;" : "=l"(r) : "l"(a), "l"(b)); return r; }
DI ull mul2(ull a, ull b){ ull r; asm("mul.rn.f32x2 %0, %1, %2;" : "=l"(r) : "l"(a), "l"(b)); return r; }
DI ull fma2(ull a, ull b, ull c){ ull r; asm("fma.rn.f32x2 %0, %1, %2, %3;" : "=l"(r) : "l"(a), "l"(b), "l"(c)); return r; }

// exact-ish gelu (sigmoid form, f32) for the action head
DI float gelu_f(float x){
  float x2 = x * x;
  float w  = x * fmaf(GK1, x2, GK0);
  return x * rcpa(1.0f + ex2a(w));
}

DI float wredmax(float v){
  #pragma unroll
  for (int o = 16; o; o >>= 1) v = fmaxf(v, __shfl_xor_sync(0xffffffffu, v, o));
  return v;
}
DI float wredsum(float v){
  #pragma unroll
  for (int o = 16; o; o >>= 1) v += __shfl_xor_sync(0xffffffffu, v, o);
  return v;
}

// ---------------- P1: five GEMMs, smem-staged W (double-buffered) -----------
// grid (BS/16, 5) = 320 CTAs, block 256 = 8 warps, 2 rows/warp.
__global__ void __launch_bounds__(256) k_gemm(
    const float* __restrict__ x,
    const float* __restrict__ W0, const float* __restrict__ Bi0,
    const float* __restrict__ W1, const float* __restrict__ Bi1,
    const float* __restrict__ W2, const float* __restrict__ Bi2,
    const float* __restrict__ W3, const float* __restrict__ Bi3,
    const float* __restrict__ W4, const float* __restrict__ Bi4,
    const float* __restrict__ lng, const float* __restrict__ lnb,
    const float* __restrict__ aw2, const float* __restrict__ ab2)
{
  __shared__ __align__(16) float xs[16][H];
  __shared__ __align__(16) float wbuf[2][16 * H];   // 2 x 8KB W chunks
  int m = blockIdx.y;
  const float* W = W0; const float* bias = Bi0;
  if      (m == 1){ W = W1; bias = Bi1; }
  else if (m == 2){ W = W2; bias = Bi2; }
  else if (m == 3){ W = W3; bias = Bi3; }
  else if (m == 4){ W = W4; bias = Bi4; }

  int r0 = blockIdx.x * 16;
  int t  = threadIdx.x;
  int wid = t >> 5, lane = t & 31;
  int c0 = lane * 4;
  int rt = wid * 2;

  #pragma unroll
  for (int k = 0; k < 2; ++k) {
    int idx = t + k * 256;
    *(float4*)&xs[idx >> 5][(idx & 31) * 4] =
        *(const float4*)&x[(r0 + (idx >> 5)) * H + (idx & 31) * 4];
  }

  const float4* Wv = (const float4*)W;
  float4 pf0 = Wv[t], pf1 = Wv[t + 256];

  float4 bv = *(const float4*)&bias[c0];
  float acc[2][4];
  #pragma unroll
  for (int i = 0; i < 2; ++i){ acc[i][0]=bv.x; acc[i][1]=bv.y; acc[i][2]=bv.z; acc[i][3]=bv.w; }

  for (int c = 0; c < 8; ++c) {
    float4* wb = (float4*)wbuf[c & 1];
    __syncthreads();
    wb[t] = pf0; wb[t + 256] = pf1;
    __syncthreads();
    if (c < 7) {
      const float4* Wn = Wv + (c + 1) * 512;
      pf0 = Wn[t]; pf1 = Wn[t + 256];
    }
    const float* wbf = wbuf[c & 1];
    #pragma unroll
    for (int hh = 0; hh < 16; ++hh) {
      int h = c * 16 + hh;
      float4 w4 = *(const float4*)&wbf[hh * H + c0];
      float xv0 = xs[rt][h], xv1 = xs[rt + 1][h];
      acc[0][0] = fmaf(xv0, w4.x, acc[0][0]);
      acc[0][1] = fmaf(xv0, w4.y, acc[0][1]);
      acc[0][2] = fmaf(xv0, w4.z, acc[0][2]);
      acc[0][3] = fmaf(xv0, w4.w, acc[0][3]);
      acc[1][0] = fmaf(xv1, w4.x, acc[1][0]);
      acc[1][1] = fmaf(xv1, w4.y, acc[1][1]);
      acc[1][2] = fmaf(xv1, w4.z, acc[1][2]);
      acc[1][3] = fmaf(xv1, w4.w, acc[1][3]);
    }
  }

  if (m == 0) {
    float4 lg4 = *(const float4*)&lng[c0];
    float4 lb4 = *(const float4*)&lnb[c0];
    #pragma unroll
    for (int i = 0; i < 2; ++i) {
      float y0 = gelu_f(acc[i][0]), y1 = gelu_f(acc[i][1]);
      float y2 = gelu_f(acc[i][2]), y3 = gelu_f(acc[i][3]);
      float s1 = wredsum(y0 + y1 + y2 + y3);
      float s2 = wredsum(y0*y0 + y1*y1 + y2*y2 + y3*y3);
      float mean = s1 * (1.0f / H);
      float var  = fmaf(-mean, mean, s2 * (1.0f / H));
      float rstd = rsqa(var + EPS);
      float z0 = fmaf((y0 - mean) * rstd, lg4.x, lb4.x);
      float z1 = fmaf((y1 - mean) * rstd, lg4.y, lb4.y);
      float z2 = fmaf((y2 - mean) * rstd, lg4.z, lb4.z);
      float z3 = fmaf((y3 - mean) * rstd, lg4.w, lb4.w);
      float r[7];
      #pragma unroll
      for (int a = 0; a < A; ++a) {
        float p = fmaf(z0, aw2[(c0+0)*A+a],
                  fmaf(z1, aw2[(c0+1)*A+a],
                  fmaf(z2, aw2[(c0+2)*A+a], z3 * aw2[(c0+3)*A+a])));
        r[a] = wredsum(p);
      }
      if (lane == 0) {
        int row = r0 + rt + i;
        #pragma unroll
        for (int a = 0; a < A; ++a) g_logits[row * A + a] = r[a] + ab2[a];
      }
    }
  } else if (m == 1 || m == 3) {
    int hh = (m == 1) ? 0 : 1;
    float4* st = (float4*)wbuf;
    __syncthreads();
    #pragma unroll
    for (int i = 0; i < 2; ++i){
      float4 o; o.x=acc[i][0]; o.y=acc[i][1]; o.z=acc[i][2]; o.w=acc[i][3];
      st[(rt + i) * 33 + lane] = o;
    }
    __syncthreads();
    #pragma unroll
    for (int k = 0; k < 2; ++k) {
      int idx = t + k * 256;
      int q2 = idx >> 4, rr = idx & 15;
      g_hvT[hh][q2][r0 + rr] = st[rr * 33 + q2];
    }
  } else {
    #pragma unroll
    for (int i = 0; i < 2; ++i){
      float4 o; o.x=acc[i][0]; o.y=acc[i][1]; o.z=acc[i][2]; o.w=acc[i][3];
      *(float4*)&g_pre[m][(r0 + rt + i) * H + c0] = o;
    }
  }
}

// ---------------- P2: action log_softmax over dim 1 (sequence) ----------------
__global__ void __launch_bounds__(512) k_actsm(float* __restrict__ out)
{
  int b = blockIdx.x / A, a = blockIdx.x % A;
  int s = threadIdx.x;
  float v = g_logits[(b * S + s) * A + a];

  __shared__ float red[16];
  __shared__ float bmax_s, bsum_s;
  int wid = s >> 5, lane = s & 31;

  float m = wredmax(v);
  if (lane == 0) red[wid] = m;
  __syncthreads();
  if (s < 32){
    float tt = (s < 16) ? red[s] : -3.4e38f;
    tt = wredmax(tt);
    if (s == 0) bmax_s = tt;
  }
  __syncthreads();
  float bmax = bmax_s;
  float e = ex2a((v - bmax) * LOG2E);
  float sm = wredsum(e);
  __syncthreads();
  if (lane == 0) red[wid] = sm;
  __syncthreads();
  if (s < 32){
    float tt = (s < 16) ? red[s] : 0.0f;
    tt = wredsum(tt);
    if (s == 0) bsum_s = tt;
  }
  __syncthreads();
  out[(b * S + s) * A + a] = v - bmax - lg2a(bsum_s) * LN2;
}

// ---------------- P4: pointer heads (f32x2 + f32 tanh, 2 i-rows/warp) --------
// grid (S/2, B, 2) = 1024 CTAs (6.9/SM), block 256 = 8 j-groups of 64 j.
// CTA owns 2 i-rows; warp g covers j in [g*64,(g+1)*64) x both rows.
// launch_bounds(256,5) -> ~40 warps/SM.
__global__ void __launch_bounds__(256, 5) k_ptr(
    const float* __restrict__ lg, const float* __restrict__ lb,
    const float* __restrict__ lpw, const float* __restrict__ lpb,
    const float* __restrict__ rg, const float* __restrict__ rb,
    const float* __restrict__ rpw, const float* __restrict__ rpb,
    float* __restrict__ out)
{
  int head = blockIdx.z, b = blockIdx.y;
  int i0 = blockIdx.x * 2;
  const float* gv = head ? rg  : lg;
  const float* bv = head ? rb  : lb;
  const float* pw = head ? rpw : lpw;
  const float* pb = head ? rpb : lpb;
  const float* hd = g_pre[2 + 2 * head] + b * S * H;   // indexed by i

  __shared__ __align__(16) float hds[2][H];
  __shared__ __align__(16) float wgh[H];
  __shared__ float redc[4][2];
  __shared__ float cc2[2];
  __shared__ float gmaxs[8][2], gsums[8][2];

  int tid  = threadIdx.x;
  int wid  = tid >> 5, lane = tid & 31;
  int g    = wid;             // j-group (0..7), 64 j each

  if (tid < 128) {
    float p  = pw[tid];
    float wg = gv[tid] * p;
    float tb = bv[tid] * p;
    wgh[tid] = wg;
    float r1 = wredsum(wg), r2 = wredsum(tb);
    if (lane == 0){ redc[wid][0] = r1; redc[wid][1] = r2; }
  }
  for (int idx = tid; idx < 2 * H; idx += 256)
    hds[idx >> 7][idx & (H - 1)] = hd[(i0 + (idx >> 7)) * H + (idx & (H - 1))];
  __syncthreads();
  if (tid == 0){
    cc2[0] = redc[0][0] + redc[1][0] + redc[2][0] + redc[3][0];
    cc2[1] = redc[0][1] + redc[1][1] + redc[2][1] + redc[3][1] + pb[0];
  }
  __syncthreads();
  float c1 = cc2[0], c2 = cc2[1];

  const ull K0p = pk2(TK0, TK0);
  const ull K1p = pk2(TK1, TK1);
  const ull* wr = (const ull*)&wgh[0];

  float sc[2][2];   // [i-row][tile]

  #pragma unroll
  for (int tile = 0; tile < 2; ++tile) {
    int jb = g * 64 + tile * 32;
    const ulonglong2* ap = (const ulonglong2*)&g_hvT[head][0][b * S + jb + lane];

    ull s1[2], s2[2], s3[2];
    #pragma unroll
    for (int r = 0; r < 2; ++r){ s1[r] = 0; s2[r] = 0; s3[r] = 0; }

    #pragma unroll 8
    for (int q2 = 0; q2 < 32; ++q2) {
      ulonglong2 a2 = ap[q2 * BS];
      #pragma unroll
      for (int half = 0; half < 2; ++half) {
        ull a = half ? a2.y : a2.x;
        ull w = wr[q2 * 2 + half];
        #pragma unroll
        for (int r = 0; r < 2; ++r) {
          ull d  = ((const ull*)&hds[r][0])[q2 * 2 + half];
          ull x  = add2(a, d);
          ull x2 = mul2(x, x);
          ull p  = fma2(K1p, x2, K0p);
          ull u  = mul2(x, p);
          float u0f, u1f; upk2(u, u0f, u1f);
          ull t  = pk2(tanha(u0f), tanha(u1f));
          ull z  = fma2(x, t, x);          // z = 2*gelu(x)
          s1[r] = add2(s1[r], z);
          s2[r] = fma2(z, z, s2[r]);
          s3[r] = fma2(z, w, s3[r]);
        }
      }
    }
    #pragma unroll
    for (int r = 0; r < 2; ++r) {
      float a0,a1,q0,q1,d0,d1;
      upk2(s1[r], a0, a1); upk2(s2[r], q0, q1); upk2(s3[r], d0, d1);
      float t1 = a0 + a1, t2 = q0 + q1, t3 = d0 + d1;
      float mean = t1 * (0.5f / H);                       // sum(y)/H, y = z/2
      float var  = fmaf(-mean, mean, t2 * (0.25f / H));
      float rstd = rsqa(var + EPS);
      sc[r][tile] = fmaf(rstd, fmaf(-mean, c1, 0.5f * t3), c2);
    }
  }

  // log_softmax over j: combine 8 j-groups per i-row
  float lm[2];
  #pragma unroll
  for (int r = 0; r < 2; ++r) {
    lm[r] = wredmax(fmaxf(sc[r][0], sc[r][1]));
    if (lane == 0) gmaxs[g][r] = lm[r];
  }
  __syncthreads();
  float mrow[2], ls[2];
  #pragma unroll
  for (int r = 0; r < 2; ++r) {
    float m = gmaxs[0][r];
    #pragma unroll
    for (int gg = 1; gg < 8; ++gg) m = fmaxf(m, gmaxs[gg][r]);
    mrow[r] = m;
    float s = ex2a((sc[r][0] - m) * LOG2E) + ex2a((sc[r][1] - m) * LOG2E);
    ls[r] = wredsum(s);
    if (lane == 0) gsums[g][r] = ls[r];
  }
  __syncthreads();
  float* obase = out + B * S * A + head * (B * S * S);
  #pragma unroll
  for (int r = 0; r < 2; ++r) {
    float s = gsums[0][r];
    #pragma unroll
    for (int gg = 1; gg < 8; ++gg) s += gsums[gg][r];
    float lse = lg2a(s) * LN2;
    float* orow = obase + (b * S + i0 + r) * S + g * 64;
    orow[lane]      = sc[r][0] - mrow[r] - lse;
    orow[32 + lane] = sc[r][1] - mrow[r] - lse;
  }
}

extern "C" void kernel_launch(void* const* d_in, const int* in_sizes, int n_in,
                              void* d_out, int out_size)
{
  (void)in_sizes; (void)n_in; (void)out_size;
  const float* hiddens = (const float*)d_in[0];
  const float* aw1     = (const float*)d_in[1];
  const float* ab1     = (const float*)d_in[2];
  const float* a_ln_g  = (const float*)d_in[3];
  const float* a_ln_b  = (const float*)d_in[4];
  const float* aw2     = (const float*)d_in[5];
  const float* ab2     = (const float*)d_in[6];
  const float* lhid_w  = (const float*)d_in[7];
  const float* lhid_b  = (const float*)d_in[8];
  const float* lhead_w = (const float*)d_in[9];
  const float* lhead_b = (const float*)d_in[10];
  const float* l_ln_g  = (const float*)d_in[11];
  const float* l_ln_b  = (const float*)d_in[12];
  const float* l_proj_w= (const float*)d_in[13];
  const float* l_proj_b= (const float*)d_in[14];
  const float* rhid_w  = (const float*)d_in[15];
  const float* rhid_b  = (const float*)d_in[16];
  const float* rhead_w = (const float*)d_in[17];
  const float* rhead_b = (const float*)d_in[18];
  const float* r_ln_g  = (const float*)d_in[19];
  const float* r_ln_b  = (const float*)d_in[20];
  const float* r_proj_w= (const float*)d_in[21];
  const float* r_proj_b= (const float*)d_in[22];
  float* out = (float*)d_out;

  k_gemm<<<dim3(BS / 16, 5), 256>>>(hiddens,
      aw1, ab1, lhid_w, lhid_b, lhead_w, lhead_b, rhid_w, rhid_b, rhead_w, rhead_b,
      a_ln_g, a_ln_b, aw2, ab2);
  k_actsm<<<B * A, 512>>>(out);
  k_ptr<<<dim3(S / 2, B, 2), 256>>>(l_ln_g, l_ln_b, l_proj_w, l_proj_b,
                                    r_ln_g, r_ln_b, r_proj_w, r_proj_b, out);
}